// round 1
// baseline (speedup 1.0000x reference)
#include <cuda_runtime.h>
#include <math.h>

#define NNODE 100000
#define NEDGE 1600000
#define TOTE  (NEDGE + NNODE)
#define SCAN_B 1024
#define NBLK_SCAN ((NNODE + SCAN_B - 1) / SCAN_B)

// ---------------- scratch (static device globals; no allocation in launch) ----
__device__ int   g_rowstart[NNODE + 1];
__device__ int   g_cursor[NNODE];
__device__ int   g_col[TOTE];
__device__ int   g_bsums[NBLK_SCAN];
__device__ float g_hp[NNODE * 128];    // projection output of current layer
__device__ float g_buf1[NNODE * 128];  // ping
__device__ float g_buf2[NNODE * 128];  // pong
__device__ float g_als[NNODE * 4];     // per-node src attention logits [N,H]
__device__ float g_ald[NNODE * 4];     // per-node dst attention logits [N,H]

// ---------------- CSR build ----------------
__global__ void k_zero_cursor() {
    int i = blockIdx.x * blockDim.x + threadIdx.x;
    if (i < NNODE) g_cursor[i] = 0;
}

__global__ void k_hist(const int* __restrict__ ei) {
    int t = blockIdx.x * blockDim.x + threadIdx.x;
    if (t >= TOTE) return;
    int dst = (t < NEDGE) ? ei[NEDGE + t] : (t - NEDGE);
    atomicAdd(&g_cursor[dst], 1);
}

__global__ void k_scan1() {
    __shared__ int sh[SCAN_B];
    int tid = threadIdx.x;
    int i = blockIdx.x * SCAN_B + tid;
    int v = (i < NNODE) ? g_cursor[i] : 0;
    sh[tid] = v;
    __syncthreads();
    #pragma unroll
    for (int off = 1; off < SCAN_B; off <<= 1) {
        int t = (tid >= off) ? sh[tid - off] : 0;
        __syncthreads();
        sh[tid] += t;
        __syncthreads();
    }
    if (i < NNODE) g_rowstart[i] = sh[tid] - v;   // exclusive, block-local
    if (tid == SCAN_B - 1) g_bsums[blockIdx.x] = sh[tid];
}

__global__ void k_scan2() {
    if (threadIdx.x == 0) {
        int acc = 0;
        for (int b = 0; b < NBLK_SCAN; b++) {
            int t = g_bsums[b];
            g_bsums[b] = acc;
            acc += t;
        }
    }
}

__global__ void k_scan3() {
    int tid = threadIdx.x;
    int i = blockIdx.x * SCAN_B + tid;
    if (i < NNODE) {
        int v = g_rowstart[i] + g_bsums[blockIdx.x];
        g_rowstart[i] = v;
        g_cursor[i] = v;
    }
    if (i == 0) g_rowstart[NNODE] = TOTE;
}

__global__ void k_scatter(const int* __restrict__ ei) {
    int t = blockIdx.x * blockDim.x + threadIdx.x;
    if (t >= TOTE) return;
    int src, dst;
    if (t < NEDGE) { src = ei[t]; dst = ei[NEDGE + t]; }
    else           { src = t - NEDGE; dst = src; }
    int pos = atomicAdd(&g_cursor[dst], 1);
    g_col[pos] = src;
}

// ---------------- SGEMM: C[M,N] = A[M,K] @ B[K,N], fp32 ----------------
__global__ __launch_bounds__(256)
void k_sgemm(const float* __restrict__ A, const float* __restrict__ B,
             float* __restrict__ C, int M, int N, int K) {
    const int BM = 64, BN = 64, BK = 16;
    __shared__ float As[BK][BM];
    __shared__ float Bs[BK][BN];
    int tid = threadIdx.x;
    int rowBase = blockIdx.x * BM;
    int colBase = blockIdx.y * BN;
    int tr = tid >> 4, tc = tid & 15;     // 16x16 thread tile, 4x4 regs each
    int aRow = tid >> 2, aKq = tid & 3;   // A loader: row, k-quad
    int bKr = tid >> 4, bCq = tid & 15;   // B loader: k-row, col-quad
    float acc[4][4];
    #pragma unroll
    for (int i = 0; i < 4; i++)
        #pragma unroll
        for (int j = 0; j < 4; j++) acc[i][j] = 0.f;

    for (int k0 = 0; k0 < K; k0 += BK) {
        float4 av = make_float4(0.f, 0.f, 0.f, 0.f);
        int gr = rowBase + aRow;
        if (gr < M) av = *(const float4*)&A[gr * K + k0 + aKq * 4];
        As[aKq * 4 + 0][aRow] = av.x;
        As[aKq * 4 + 1][aRow] = av.y;
        As[aKq * 4 + 2][aRow] = av.z;
        As[aKq * 4 + 3][aRow] = av.w;
        float4 bv = *(const float4*)&B[(k0 + bKr) * N + colBase + bCq * 4];
        *(float4*)&Bs[bKr][bCq * 4] = bv;
        __syncthreads();
        #pragma unroll
        for (int k = 0; k < BK; k++) {
            float4 a = *(const float4*)&As[k][tr * 4];
            float4 b = *(const float4*)&Bs[k][tc * 4];
            acc[0][0] += a.x * b.x; acc[0][1] += a.x * b.y; acc[0][2] += a.x * b.z; acc[0][3] += a.x * b.w;
            acc[1][0] += a.y * b.x; acc[1][1] += a.y * b.y; acc[1][2] += a.y * b.z; acc[1][3] += a.y * b.w;
            acc[2][0] += a.z * b.x; acc[2][1] += a.z * b.y; acc[2][2] += a.z * b.z; acc[2][3] += a.z * b.w;
            acc[3][0] += a.w * b.x; acc[3][1] += a.w * b.y; acc[3][2] += a.w * b.z; acc[3][3] += a.w * b.w;
        }
        __syncthreads();
    }
    #pragma unroll
    for (int i = 0; i < 4; i++) {
        int gr = rowBase + tr * 4 + i;
        if (gr < M) {
            float4 o = make_float4(acc[i][0], acc[i][1], acc[i][2], acc[i][3]);
            *(float4*)&C[gr * N + colBase + tc * 4] = o;
        }
    }
}

// ---------------- per-node attention logits: al_s/al_d [N,H] ----------------
template <int OUT>
__global__ void k_al(const float* __restrict__ hp,
                     const float* __restrict__ a_src,
                     const float* __restrict__ a_dst) {
    int gw = (blockIdx.x * blockDim.x + threadIdx.x) >> 5;
    int lane = threadIdx.x & 31;
    if (gw >= NNODE) return;
    int n = gw;
    float ps, pd;
    if (OUT == 128) {
        float4 h = *(const float4*)&hp[n * 128 + lane * 4];
        float4 s = *(const float4*)&a_src[lane * 4];
        float4 d = *(const float4*)&a_dst[lane * 4];
        ps = h.x * s.x + h.y * s.y + h.z * s.z + h.w * s.w;
        pd = h.x * d.x + h.y * d.y + h.z * d.z + h.w * d.w;
    } else {
        float2 h = *(const float2*)&hp[n * 64 + lane * 2];
        float2 s = *(const float2*)&a_src[lane * 2];
        float2 d = *(const float2*)&a_dst[lane * 2];
        ps = h.x * s.x + h.y * s.y;
        pd = h.x * d.x + h.y * d.y;
    }
    // reduce within each 8-lane head group
    #pragma unroll
    for (int o = 4; o >= 1; o >>= 1) {
        ps += __shfl_down_sync(0xffffffffu, ps, o, 8);
        pd += __shfl_down_sync(0xffffffffu, pd, o, 8);
    }
    if ((lane & 7) == 0) {
        int h = lane >> 3;
        g_als[n * 4 + h] = ps;
        g_ald[n * 4 + h] = pd;
    }
}

// ---------------- softmax + aggregation, warp per dst node ----------------
#define WPB 4
template <int OUT>
__global__ __launch_bounds__(128)
void k_agg(const float* __restrict__ hp,
           const float* __restrict__ bias,
           float* __restrict__ hout) {
    __shared__ int   sh_src[WPB][32];
    __shared__ float sh_ex[WPB][4][32];   // head-major: conflict-free
    int w = threadIdx.x >> 5;
    int lane = threadIdx.x & 31;
    int n = blockIdx.x * WPB + w;
    if (n >= NNODE) return;
    int head = lane >> 3;
    int rs = g_rowstart[n], re = g_rowstart[n + 1];
    float ad0 = g_ald[n * 4 + 0], ad1 = g_ald[n * 4 + 1];
    float ad2 = g_ald[n * 4 + 2], ad3 = g_ald[n * 4 + 3];

    // pass 1: per-head max of leaky_relu(al_s[src] + al_d[dst])
    float m0 = -1e30f, m1 = -1e30f, m2 = -1e30f, m3 = -1e30f;
    for (int j = rs + lane; j < re; j += 32) {
        int s = g_col[j];
        float4 as = *(const float4*)&g_als[s * 4];
        float e0 = as.x + ad0; e0 = (e0 > 0.f) ? e0 : 0.2f * e0; m0 = fmaxf(m0, e0);
        float e1 = as.y + ad1; e1 = (e1 > 0.f) ? e1 : 0.2f * e1; m1 = fmaxf(m1, e1);
        float e2 = as.z + ad2; e2 = (e2 > 0.f) ? e2 : 0.2f * e2; m2 = fmaxf(m2, e2);
        float e3 = as.w + ad3; e3 = (e3 > 0.f) ? e3 : 0.2f * e3; m3 = fmaxf(m3, e3);
    }
    #pragma unroll
    for (int o = 16; o >= 1; o >>= 1) {
        m0 = fmaxf(m0, __shfl_xor_sync(0xffffffffu, m0, o));
        m1 = fmaxf(m1, __shfl_xor_sync(0xffffffffu, m1, o));
        m2 = fmaxf(m2, __shfl_xor_sync(0xffffffffu, m2, o));
        m3 = fmaxf(m3, __shfl_xor_sync(0xffffffffu, m3, o));
    }

    // pass 2: accumulate ex and ex * h[src] (unnormalized), chunk by 32 edges
    float acc0 = 0.f, acc1 = 0.f, acc2 = 0.f, acc3 = 0.f;
    float ds0 = 0.f, ds1 = 0.f, ds2 = 0.f, ds3 = 0.f;
    for (int base = rs; base < re; base += 32) {
        int j = base + lane;
        int cnt = min(32, re - base);
        if (j < re) {
            int s = g_col[j];
            float4 as = *(const float4*)&g_als[s * 4];
            float e0 = as.x + ad0; e0 = (e0 > 0.f) ? e0 : 0.2f * e0;
            float e1 = as.y + ad1; e1 = (e1 > 0.f) ? e1 : 0.2f * e1;
            float e2 = as.z + ad2; e2 = (e2 > 0.f) ? e2 : 0.2f * e2;
            float e3 = as.w + ad3; e3 = (e3 > 0.f) ? e3 : 0.2f * e3;
            float x0 = __expf(e0 - m0); ds0 += x0;
            float x1 = __expf(e1 - m1); ds1 += x1;
            float x2 = __expf(e2 - m2); ds2 += x2;
            float x3 = __expf(e3 - m3); ds3 += x3;
            sh_src[w][lane] = s;
            sh_ex[w][0][lane] = x0;
            sh_ex[w][1][lane] = x1;
            sh_ex[w][2][lane] = x2;
            sh_ex[w][3][lane] = x3;
        }
        __syncwarp();
        for (int t = 0; t < cnt; t++) {
            int s = sh_src[w][t];
            float ex = sh_ex[w][head][t];
            if (OUT == 128) {
                float4 hv = *(const float4*)&hp[s * 128 + lane * 4];
                acc0 += ex * hv.x; acc1 += ex * hv.y;
                acc2 += ex * hv.z; acc3 += ex * hv.w;
            } else {
                float2 hv = *(const float2*)&hp[s * 64 + lane * 2];
                acc0 += ex * hv.x; acc1 += ex * hv.y;
            }
        }
        __syncwarp();
    }
    #pragma unroll
    for (int o = 16; o >= 1; o >>= 1) {
        ds0 += __shfl_xor_sync(0xffffffffu, ds0, o);
        ds1 += __shfl_xor_sync(0xffffffffu, ds1, o);
        ds2 += __shfl_xor_sync(0xffffffffu, ds2, o);
        ds3 += __shfl_xor_sync(0xffffffffu, ds3, o);
    }
    float den = (head == 0) ? ds0 : (head == 1) ? ds1 : (head == 2) ? ds2 : ds3;
    float inv = 1.f / (den + 1e-16f);
    if (OUT == 128) {
        float4 bv = *(const float4*)&bias[lane * 4];
        float4 o4;
        o4.x = fmaxf(acc0 * inv + bv.x, 0.f);
        o4.y = fmaxf(acc1 * inv + bv.y, 0.f);
        o4.z = fmaxf(acc2 * inv + bv.z, 0.f);
        o4.w = fmaxf(acc3 * inv + bv.w, 0.f);
        *(float4*)&hout[n * 128 + lane * 4] = o4;
    } else {
        float2 bv = *(const float2*)&bias[lane * 2];
        float2 o2;
        o2.x = fmaxf(acc0 * inv + bv.x, 0.f);
        o2.y = fmaxf(acc1 * inv + bv.y, 0.f);
        *(float2*)&hout[n * 64 + lane * 2] = o2;
    }
}

// ---------------- classifier: out[N,40] = h[N,64] @ Wc[64,40] + bc ----------
__global__ __launch_bounds__(256)
void k_classify(const float* __restrict__ h,
                const float* __restrict__ Wc,
                const float* __restrict__ bc,
                float* __restrict__ out) {
    __shared__ float shW[64 * 40];
    __shared__ float shb[40];
    __shared__ float shh[8][64];
    int tid = threadIdx.x;
    for (int i = tid; i < 64 * 40; i += 256) shW[i] = Wc[i];
    if (tid < 40) shb[tid] = bc[tid];
    __syncthreads();
    int w = tid >> 5, lane = tid & 31;
    int n = blockIdx.x * 8 + w;
    if (n >= NNODE) return;
    float2 hv = *(const float2*)&h[n * 64 + lane * 2];
    shh[w][lane * 2] = hv.x;
    shh[w][lane * 2 + 1] = hv.y;
    __syncwarp();
    float a0 = shb[lane];
    float a1 = (lane < 8) ? shb[32 + lane] : 0.f;
    #pragma unroll
    for (int k = 0; k < 64; k++) {
        float hk = shh[w][k];
        a0 += hk * shW[k * 40 + lane];
        if (lane < 8) a1 += hk * shW[k * 40 + 32 + lane];
    }
    out[n * 40 + lane] = a0;
    if (lane < 8) out[n * 40 + 32 + lane] = a1;
}

// ---------------- launch ----------------
extern "C" void kernel_launch(void* const* d_in, const int* in_sizes, int n_in,
                              void* d_out, int out_size) {
    // Identify inputs by element count; same-size params keep relative order
    // in both plausible metadata orderings:
    //   W0,a_src0,a_dst0,b0, W1,a_src1,a_dst1,b1, W2,a_src2,a_dst2,b2, Wc,bc
    const float* x = nullptr;
    const int* ei = nullptr;
    const float* P[16];
    int np = 0;
    for (int i = 0; i < n_in; i++) {
        if (in_sizes[i] == NNODE * 128)      x = (const float*)d_in[i];
        else if (in_sizes[i] == 2 * NEDGE)   ei = (const int*)d_in[i];
        else if (np < 16)                    P[np++] = (const float*)d_in[i];
    }
    float *hp, *b1, *b2;
    cudaGetSymbolAddress((void**)&hp, g_hp);
    cudaGetSymbolAddress((void**)&b1, g_buf1);
    cudaGetSymbolAddress((void**)&b2, g_buf2);
    float* out = (float*)d_out;

    // ---- CSR build (dst-indexed) ----
    k_zero_cursor<<<(NNODE + 255) / 256, 256>>>();
    k_hist<<<(TOTE + 255) / 256, 256>>>(ei);
    k_scan1<<<NBLK_SCAN, SCAN_B>>>();
    k_scan2<<<1, 32>>>();
    k_scan3<<<NBLK_SCAN, SCAN_B>>>();
    k_scatter<<<(TOTE + 255) / 256, 256>>>(ei);

    dim3 g128((NNODE + 63) / 64, 2);
    dim3 g64n((NNODE + 63) / 64, 1);
    int nwgrid = (NNODE + WPB - 1) / WPB;

    // ---- layer 0: x(128) -> 128 ----
    k_sgemm<<<g128, 256>>>(x, P[0], hp, NNODE, 128, 128);
    k_al<128><<<nwgrid, 128>>>(hp, P[1], P[2]);
    k_agg<128><<<nwgrid, 128>>>(hp, P[3], b1);
    // ---- layer 1: 128 -> 128 ----
    k_sgemm<<<g128, 256>>>(b1, P[4], hp, NNODE, 128, 128);
    k_al<128><<<nwgrid, 128>>>(hp, P[5], P[6]);
    k_agg<128><<<nwgrid, 128>>>(hp, P[7], b2);
    // ---- layer 2: 128 -> 64 ----
    k_sgemm<<<g64n, 256>>>(b2, P[8], hp, NNODE, 64, 128);
    k_al<64><<<nwgrid, 128>>>(hp, P[9], P[10]);
    k_agg<64><<<nwgrid, 128>>>(hp, P[11], b1);
    // ---- classifier: 64 -> 40 ----
    k_classify<<<(NNODE + 7) / 8, 256>>>(b1, P[12], P[13], out);
}